// round 1
// baseline (speedup 1.0000x reference)
#include <cuda_runtime.h>

#define NN 20000
#define NE 320000
#define FULLMASK 0xffffffffu
#define CSTF 1e-5f

// ---------------- device scratch (static, no allocation) ----------------
__device__ float g_Q[NN*64];
__device__ float g_Kf[NN*64];
__device__ float g_V[NN*64];
__device__ float g_K1[NN*64];
__device__ float g_hidden[NN*64];
__device__ float g_M1[(size_t)NN*512];   // [n][h][i][j] = n*512 + h*64 + i*8 + j
__device__ float g_deginv[NN];
__device__ int   g_cnt[NN];
__device__ int   g_cur[NN];
__device__ int   g_colptr[NN+1];
__device__ int   g_srow[NE];
__device__ float g_snorm[NE];
__device__ float g_gamma[16];            // [hop][head]
__device__ float g_hop0;
__device__ int   g_is64;

// ---------------- small setup kernels ----------------
__global__ void k_zero(){
  int i = blockIdx.x*blockDim.x + threadIdx.x;
  if(i < NN) g_cnt[i] = 0;
  else if(i < 2*NN) g_cur[i-NN] = 0;
}

// Detect whether edge_index arrived as int64 (JAX x64 on) or int32 (default).
// If int64: the int32 view's odd words (high halves of values < 2^31) are all 0.
__global__ void k_detect(const int* __restrict__ ei){
  int lane = threadIdx.x;
  bool z = true;
  for(int k=0;k<8;k++){
    int m = lane*8 + k;              // 0..255
    int w = 2*m*1200 + 1;            // odd word, < 612002 < 640000 (safe either way)
    if(ei[w] != 0) z = false;
  }
  unsigned bal = __ballot_sync(FULLMASK, z);
  if(lane==0) g_is64 = (bal == FULLMASK) ? 1 : 0;
}

__device__ __forceinline__ int edge_row(const int* ei, int e){
  return g_is64 ? ei[2*e] : ei[e];
}
__device__ __forceinline__ int edge_col(const int* ei, int e){
  return g_is64 ? ei[2*(NE+e)] : ei[NE+e];
}

__global__ void k_hist(const int* __restrict__ ei){
  int e = blockIdx.x*blockDim.x + threadIdx.x;
  if(e < NE) atomicAdd(&g_cnt[edge_col(ei,e)], 1);
}

// exclusive prefix over 20000 counts + deg^-0.5 ; single block of 1024
__global__ void k_scan(){
  const int CH = 20;
  int t = threadIdx.x;
  int lane = t & 31, wid = t >> 5;
  int base = t*CH;
  int c[CH]; int s = 0;
  #pragma unroll
  for(int k=0;k<CH;k++){ int idx = base+k; int v = (idx<NN)? g_cnt[idx] : 0; c[k]=v; s+=v; }
  __shared__ int wsum[32];
  int x = s;
  #pragma unroll
  for(int off=1; off<32; off<<=1){ int y=__shfl_up_sync(FULLMASK,x,off); if(lane>=off) x+=y; }
  if(lane==31) wsum[wid] = x;
  __syncthreads();
  if(wid==0){
    int w = wsum[lane];
    #pragma unroll
    for(int off=1; off<32; off<<=1){ int y=__shfl_up_sync(FULLMASK,w,off); if(lane>=off) w+=y; }
    wsum[lane] = w;
  }
  __syncthreads();
  int run = x - s + (wid>0 ? wsum[wid-1] : 0);
  #pragma unroll
  for(int k=0;k<CH;k++){
    int idx = base+k;
    if(idx < NN){
      g_colptr[idx] = run;
      g_deginv[idx] = (c[k] > 0) ? rsqrtf((float)c[k]) : 0.f;
      run += c[k];
    }
  }
  if(t==1023) g_colptr[NN] = run;
}

// gamma[hop][h] = hopwise[hop+1] * softmax_over_heads(headwise[:,hop])[h]
__global__ void k_gamma(const float* __restrict__ hopwise, const float* __restrict__ headwise){
  int t = threadIdx.x;
  if(t < 16){
    int h = t & 7, hop = t >> 3;
    float m = -1e30f;
    for(int hh=0; hh<8; hh++) m = fmaxf(m, headwise[hh*2+hop]);
    float ssum = 0.f;
    for(int hh=0; hh<8; hh++) ssum += expf(headwise[hh*2+hop]-m);
    g_gamma[hop*8+h] = hopwise[hop+1] * expf(headwise[h*2+hop]-m) / ssum;
  }
  if(t==16) g_hop0 = hopwise[0];
}

__global__ void k_scatter(const int* __restrict__ ei){
  int e = blockIdx.x*blockDim.x + threadIdx.x;
  if(e < NE){
    int r = edge_row(ei,e), cc = edge_col(ei,e);
    int pos = g_colptr[cc] + atomicAdd(&g_cur[cc], 1);
    g_srow[pos]  = r;
    g_snorm[pos] = g_deginv[r] * g_deginv[cc];
  }
}

// ---------------- dense 64x64 GEMM: out[n,o] = act(b[o] + sum_i in[n,i]*W[i,o]) ----------------
// sel: 0->g_Q(act) 1->g_Kf(act) 2->g_V 3->(in=g_hidden, out=dout)
__global__ void __launch_bounds__(256) k_gemm64(const float* __restrict__ xin,
                                                const float* __restrict__ W,
                                                const float* __restrict__ b,
                                                float* __restrict__ dout, int sel){
  const float* in = (sel==3) ? g_hidden : xin;
  float* out = (sel==0) ? g_Q : (sel==1) ? g_Kf : (sel==2) ? g_V : dout;
  __shared__ __align__(16) float xs[64*68];
  __shared__ float ws[64*64];
  __shared__ float bs[64];
  int nb = blockIdx.x*64;
  int tid = threadIdx.x;
  for(int idx = tid; idx < 4096; idx += 256){
    int n = idx >> 6, i = idx & 63;
    xs[n*68+i] = (nb+n < NN) ? in[(nb+n)*64 + i] : 0.f;
    ws[idx] = W[idx];
  }
  if(tid < 64) bs[tid] = b[tid];
  __syncthreads();
  int o  = tid & 63;
  int ng = (tid >> 6) << 4;   // 16-node group
  float acc[16];
  #pragma unroll
  for(int k=0;k<16;k++) acc[k] = bs[o];
  #pragma unroll 4
  for(int i4=0; i4<64; i4+=4){
    float w0 = ws[(i4+0)*64+o], w1 = ws[(i4+1)*64+o];
    float w2 = ws[(i4+2)*64+o], w3 = ws[(i4+3)*64+o];
    #pragma unroll
    for(int k=0;k<16;k++){
      float4 xv = *(const float4*)&xs[(ng+k)*68 + i4];
      acc[k] = fmaf(xv.x, w0, fmaf(xv.y, w1, fmaf(xv.z, w2, fmaf(xv.w, w3, acc[k]))));
    }
  }
  #pragma unroll
  for(int k=0;k<16;k++){
    int n = nb + ng + k;
    if(n < NN){
      float z = acc[k];
      if(sel < 2) z = (z > 0.f) ? (z + 1.f) : __expf(z);   // 1 + elu
      out[n*64 + o] = z;
    }
  }
}

// ---------------- hop 1: M1 = A*(K outer V), K1 = A*K, hidden = V*hop0 + g1*(Q.M1)/(Q.K1+CST) ----------------
// one warp per node; lane = h*8+i for halves (h in 0..3 / 4..7)
__global__ void __launch_bounds__(256) k_pass1(){
  int n    = (blockIdx.x*256 + threadIdx.x) >> 5;   // grid is exactly 20000 warps
  int lane = threadIdx.x & 31;
  int beg = g_colptr[n], end = g_colptr[n+1];
  int gb = lane & ~7;
  float m0[8], m1[8];
  #pragma unroll
  for(int j=0;j<8;j++){ m0[j]=0.f; m1[j]=0.f; }
  float ka0 = 0.f, ka1 = 0.f;
  for(int e=beg; e<end; e++){
    int row   = g_srow[e];
    float nrm = g_snorm[e];
    const float* Kr = &g_Kf[row*64];
    const float* Vr = &g_V[row*64];
    float k0 = Kr[lane], k1 = Kr[lane+32];
    float v0 = Vr[lane], v1 = Vr[lane+32];
    float a0 = nrm*k0, a1 = nrm*k1;
    ka0 += a0; ka1 += a1;
    #pragma unroll
    for(int j=0;j<8;j++){
      float vj0 = __shfl_sync(FULLMASK, v0, gb+j);
      float vj1 = __shfl_sync(FULLMASK, v1, gb+j);
      m0[j] = fmaf(a0, vj0, m0[j]);
      m1[j] = fmaf(a1, vj1, m1[j]);
    }
  }
  // store M1 [h][i][j] : half0 at lane*8, half1 at 256+lane*8 (both = h*64+i*8)
  float* Mrow = &g_M1[(size_t)n*512];
  *(float4*)&Mrow[lane*8]       = make_float4(m0[0],m0[1],m0[2],m0[3]);
  *(float4*)&Mrow[lane*8+4]     = make_float4(m0[4],m0[5],m0[6],m0[7]);
  *(float4*)&Mrow[256+lane*8]   = make_float4(m1[0],m1[1],m1[2],m1[3]);
  *(float4*)&Mrow[256+lane*8+4] = make_float4(m1[4],m1[5],m1[6],m1[7]);
  g_K1[n*64+lane]    = ka0;
  g_K1[n*64+lane+32] = ka1;

  // fused H1 = Q.M1 via smem transpose (row pad 9 -> conflict free)
  __shared__ float buf[8][576];
  float* bw = buf[threadIdx.x >> 5];
  #pragma unroll
  for(int j=0;j<8;j++){ bw[lane*9+j] = m0[j]; bw[(32+lane)*9+j] = m1[j]; }
  __syncwarp();
  float q0 = g_Q[n*64+lane], q1 = g_Q[n*64+lane+32];
  int j = lane & 7;
  float h0 = 0.f, h1 = 0.f;
  #pragma unroll
  for(int i=0;i<8;i++){
    float qi0 = __shfl_sync(FULLMASK, q0, gb+i);
    float qi1 = __shfl_sync(FULLMASK, q1, gb+i);
    h0 = fmaf(qi0, bw[(gb+i)*9 + j],    h0);
    h1 = fmaf(qi1, bw[(32+gb+i)*9 + j], h1);
  }
  float c0 = q0*ka0, c1 = q1*ka1;
  #pragma unroll
  for(int off=1; off<8; off<<=1){
    c0 += __shfl_xor_sync(FULLMASK, c0, off);
    c1 += __shfl_xor_sync(FULLMASK, c1, off);
  }
  c0 += CSTF; c1 += CSTF;
  float g0 = g_gamma[lane>>3], g1 = g_gamma[4 + (lane>>3)];
  float hp0 = g_hop0;
  float vv0 = g_V[n*64+lane], vv1 = g_V[n*64+lane+32];
  g_hidden[n*64+lane]    = fmaf(vv0, hp0, g0*h0/c0);
  g_hidden[n*64+lane+32] = fmaf(vv1, hp0, g1*h1/c1);
}

// ---------------- hop 2: hidden += g2 * (Q . (A*M1)) / (Q . (A*K1) + CST), no M2 materialization ----------------
__global__ void __launch_bounds__(256) k_pass3(){
  int n    = (blockIdx.x*256 + threadIdx.x) >> 5;
  int lane = threadIdx.x & 31;
  int beg = g_colptr[n], end = g_colptr[n+1];
  float q0 = g_Q[n*64+lane], q1 = g_Q[n*64+lane+32];
  float4 m[4];
  #pragma unroll
  for(int w=0;w<4;w++) m[w] = make_float4(0.f,0.f,0.f,0.f);
  float ka0 = 0.f, ka1 = 0.f;
  for(int e=beg; e<end; e++){
    int row   = g_srow[e];
    float nrm = g_snorm[e];
    const float4* Mr = (const float4*)&g_M1[(size_t)row*512];
    #pragma unroll
    for(int w=0;w<4;w++){
      float4 mv = Mr[w*32 + lane];     // element id e4 = (w*32+lane)*4 + c
      m[w].x = fmaf(nrm, mv.x, m[w].x);
      m[w].y = fmaf(nrm, mv.y, m[w].y);
      m[w].z = fmaf(nrm, mv.z, m[w].z);
      m[w].w = fmaf(nrm, mv.w, m[w].w);
    }
    const float* K1r = &g_K1[row*64];
    ka0 = fmaf(nrm, K1r[lane],    ka0);
    ka1 = fmaf(nrm, K1r[lane+32], ka1);
  }
  // contract accumulated M2 with Q: per element, Q index = e4>>3 = w*16 + (lane>>1)
  float h2[4][4];
  #pragma unroll
  for(int w=0;w<4;w++){
    int el = w*16 + (lane>>1);
    float qv = (w < 2) ? __shfl_sync(FULLMASK, q0, el)
                       : __shfl_sync(FULLMASK, q1, el-32);
    float p0 = qv*m[w].x, p1 = qv*m[w].y, p2 = qv*m[w].z, p3 = qv*m[w].w;
    #pragma unroll
    for(int off=2; off<16; off<<=1){        // i lives in lane bits 1..3
      p0 += __shfl_xor_sync(FULLMASK, p0, off);
      p1 += __shfl_xor_sync(FULLMASK, p1, off);
      p2 += __shfl_xor_sync(FULLMASK, p2, off);
      p3 += __shfl_xor_sync(FULLMASK, p3, off);
    }
    h2[w][0]=p0; h2[w][1]=p1; h2[w][2]=p2; h2[w][3]=p3;
  }
  float c0 = q0*ka0, c1 = q1*ka1;
  #pragma unroll
  for(int off=1; off<8; off<<=1){
    c0 += __shfl_xor_sync(FULLMASK, c0, off);
    c1 += __shfl_xor_sync(FULLMASK, c1, off);
  }
  __shared__ float cbuf[8][8];
  float* cb = cbuf[threadIdx.x >> 5];
  if((lane & 7) == 0){
    cb[lane>>3]     = c0 + CSTF;
    cb[4+(lane>>3)] = c1 + CSTF;
  }
  __syncwarp();
  if((lane & 14) == 0){   // lanes 0,1,16,17 own distinct float4 outputs
    #pragma unroll
    for(int w=0;w<4;w++){
      int h = w*2 + (lane>>4);
      float inv = g_gamma[8+h] / cb[h];
      int off = h*8 + (lane&1)*4;
      float4* hp = (float4*)&g_hidden[n*64 + off];
      float4 hv = *hp;
      hv.x += inv*h2[w][0];
      hv.y += inv*h2[w][1];
      hv.z += inv*h2[w][2];
      hv.w += inv*h2[w][3];
      *hp = hv;
    }
  }
}

// ---------------- launch ----------------
extern "C" void kernel_launch(void* const* d_in, const int* in_sizes, int n_in,
                              void* d_out, int out_size){
  const float* x        = (const float*)d_in[0];
  const int*   ei       = (const int*)  d_in[1];
  const float* Wq       = (const float*)d_in[3];
  const float* bq       = (const float*)d_in[4];
  const float* Wk       = (const float*)d_in[5];
  const float* bk       = (const float*)d_in[6];
  const float* Wv       = (const float*)d_in[7];
  const float* bv       = (const float*)d_in[8];
  const float* Wo       = (const float*)d_in[9];
  const float* bo       = (const float*)d_in[10];
  const float* hopwise  = (const float*)d_in[11];
  const float* headwise = (const float*)d_in[12];
  float* out = (float*)d_out;

  k_zero   <<<(2*NN+1023)/1024, 1024>>>();
  k_detect <<<1, 32>>>(ei);
  k_hist   <<<(NE+255)/256, 256>>>(ei);
  k_scan   <<<1, 1024>>>();
  k_gamma  <<<1, 32>>>(hopwise, headwise);
  k_scatter<<<(NE+255)/256, 256>>>(ei);
  k_gemm64 <<<(NN+63)/64, 256>>>(x, Wq, bq, out, 0);
  k_gemm64 <<<(NN+63)/64, 256>>>(x, Wk, bk, out, 1);
  k_gemm64 <<<(NN+63)/64, 256>>>(x, Wv, bv, out, 2);
  k_pass1  <<<NN/8, 256>>>();
  k_pass3  <<<NN/8, 256>>>();
  k_gemm64 <<<(NN+63)/64, 256>>>(x, Wo, bo, out, 3);
}

// round 2
// speedup vs baseline: 1.4837x; 1.4837x over previous
#include <cuda_runtime.h>
#include <cuda_fp16.h>

#define NN 20000
#define NE 320000
#define NB 25
#define SEG 800
#define FULLMASK 0xffffffffu
#define CSTF 1e-5f

// ---------------- device scratch (static, no allocation) ----------------
__device__ float  g_Q[NN*64];
__device__ float  g_Kf[NN*64];
__device__ float  g_V[NN*64];
__device__ float  g_hidden[NN*64];
__device__ __half g_M1h[(size_t)NN*512];   // [n][el], el = h*64+i*8+j
__device__ __half g_K1h[NN*64];            // [n][h*8+i]
__device__ float  g_deginv[NN];
__device__ int    g_cnt[NN];
__device__ int    g_cur[NN];
__device__ int    g_colptr[NN+1];          // block-local exclusive scan
__device__ int    g_bsum[NB];
__device__ int    g_boff[NB+1];
__device__ int    g_srow[NE];
__device__ float  g_snorm[NE];
__device__ float  g_gamma[16];             // [hop][head]
__device__ float  g_hop0;
__device__ int    g_is64;

// ---------------- init: zero counters + dtype detect + gamma ----------------
__global__ void k_init(const int* __restrict__ ei,
                       const float* __restrict__ hopwise,
                       const float* __restrict__ headwise){
  int i = blockIdx.x*blockDim.x + threadIdx.x;
  if(i < NN) g_cnt[i] = 0;
  else if(i < 2*NN) g_cur[i-NN] = 0;
  if(blockIdx.x == 0){
    int t = threadIdx.x;
    if(t < 32){
      // int64 vs int32 detect: odd words (high halves) all zero => int64
      bool z = true;
      for(int k=0;k<8;k++){
        int m = t*8 + k;                 // 0..255
        int w = 2*m*1200 + 1;            // < 612002, safe either way
        if(ei[w] != 0) z = false;
      }
      unsigned bal = __ballot_sync(FULLMASK, z);
      if(t==0) g_is64 = (bal == FULLMASK) ? 1 : 0;
    } else if(t < 64){
      int u = t - 32;
      if(u < 16){
        int h = u & 7, hop = u >> 3;
        float m = -1e30f;
        for(int hh=0; hh<8; hh++) m = fmaxf(m, headwise[hh*2+hop]);
        float ssum = 0.f;
        for(int hh=0; hh<8; hh++) ssum += expf(headwise[hh*2+hop]-m);
        g_gamma[hop*8+h] = hopwise[hop+1] * expf(headwise[h*2+hop]-m) / ssum;
      }
      if(u==16) g_hop0 = hopwise[0];
      if(u==17) g_colptr[NN] = 0;
    }
  }
}

__device__ __forceinline__ int edge_row(const int* ei, int e){
  return g_is64 ? ei[2*e] : ei[e];
}
__device__ __forceinline__ int edge_col(const int* ei, int e){
  return g_is64 ? ei[2*(NE+e)] : ei[NE+e];
}
__device__ __forceinline__ int colp(int i){
  return g_colptr[i] + g_boff[i/SEG];
}

__global__ void k_hist(const int* __restrict__ ei){
  int e = blockIdx.x*blockDim.x + threadIdx.x;
  if(e < NE) atomicAdd(&g_cnt[edge_col(ei,e)], 1);
}

// ---------------- scan phase 1: per-block local exclusive scan + deginv ----------------
__global__ void __launch_bounds__(256) k_scan1(){
  __shared__ int s[SEG];
  __shared__ int wtot[8];
  int b = blockIdx.x, tid = threadIdx.x;
  for(int i=tid; i<SEG; i+=256) s[i] = g_cnt[b*SEG+i];
  __syncthreads();
  int c0=0,c1=0,c2=0,c3=0,v=0;
  if(tid < 200){
    c0=s[4*tid]; c1=s[4*tid+1]; c2=s[4*tid+2]; c3=s[4*tid+3];
    v = c0+c1+c2+c3;
  }
  int lane = tid & 31, wid = tid >> 5;
  int x = v;
  #pragma unroll
  for(int off=1; off<32; off<<=1){ int y=__shfl_up_sync(FULLMASK,x,off); if(lane>=off) x+=y; }
  if(lane==31) wtot[wid] = x;
  __syncthreads();
  if(tid < 32){
    int w = (tid < 7) ? wtot[tid] : 0;
    #pragma unroll
    for(int off=1; off<32; off<<=1){ int y=__shfl_up_sync(FULLMASK,w,off); if(tid>=off) w+=y; }
    if(tid < 7) wtot[tid] = w;
    if(tid == 6) g_bsum[b] = w;
  }
  __syncthreads();
  if(tid < 200){
    int pre = x - v + (wid>0 ? wtot[wid-1] : 0);
    int base = b*SEG + 4*tid;
    g_colptr[base+0] = pre;
    g_colptr[base+1] = pre + c0;
    g_colptr[base+2] = pre + c0 + c1;
    g_colptr[base+3] = pre + c0 + c1 + c2;
    g_deginv[base+0] = c0 ? rsqrtf((float)c0) : 0.f;
    g_deginv[base+1] = c1 ? rsqrtf((float)c1) : 0.f;
    g_deginv[base+2] = c2 ? rsqrtf((float)c2) : 0.f;
    g_deginv[base+3] = c3 ? rsqrtf((float)c3) : 0.f;
  }
}

// ---------------- scan phase 2: block offsets (1 warp) ----------------
__global__ void k_scan2(){
  int t = threadIdx.x;
  int v = (t < NB) ? g_bsum[t] : 0;
  int x = v;
  #pragma unroll
  for(int off=1; off<32; off<<=1){ int y=__shfl_up_sync(FULLMASK,x,off); if(t>=off) x+=y; }
  if(t < NB) g_boff[t] = x - v;
  if(t == 31) g_boff[NB] = NE;
}

__global__ void k_scatter(const int* __restrict__ ei){
  int e = blockIdx.x*blockDim.x + threadIdx.x;
  if(e < NE){
    int r = edge_row(ei,e), cc = edge_col(ei,e);
    int pos = colp(cc) + atomicAdd(&g_cur[cc], 1);
    g_srow[pos]  = r;
    g_snorm[pos] = g_deginv[r] * g_deginv[cc];
  }
}

// ---------------- dense 64x64 GEMM body ----------------
__device__ __forceinline__ void gemm64_body(const float* __restrict__ in,
                                            const float* __restrict__ W,
                                            const float* __restrict__ b,
                                            float* __restrict__ out, bool act){
  __shared__ __align__(16) float xs[64*68];
  __shared__ float ws[64*64];
  __shared__ float bs[64];
  int nb = blockIdx.x*64;
  int tid = threadIdx.x;
  for(int idx = tid; idx < 4096; idx += 256){
    int n = idx >> 6, i = idx & 63;
    xs[n*68+i] = (nb+n < NN) ? in[(nb+n)*64 + i] : 0.f;
    ws[idx] = W[idx];
  }
  if(tid < 64) bs[tid] = b[tid];
  __syncthreads();
  int o  = tid & 63;
  int ng = (tid >> 6) << 4;
  float acc[16];
  #pragma unroll
  for(int k=0;k<16;k++) acc[k] = bs[o];
  #pragma unroll 4
  for(int i4=0; i4<64; i4+=4){
    float w0 = ws[(i4+0)*64+o], w1 = ws[(i4+1)*64+o];
    float w2 = ws[(i4+2)*64+o], w3 = ws[(i4+3)*64+o];
    #pragma unroll
    for(int k=0;k<16;k++){
      float4 xv = *(const float4*)&xs[(ng+k)*68 + i4];
      acc[k] = fmaf(xv.x, w0, fmaf(xv.y, w1, fmaf(xv.z, w2, fmaf(xv.w, w3, acc[k]))));
    }
  }
  #pragma unroll
  for(int k=0;k<16;k++){
    int n = nb + ng + k;
    if(n < NN){
      float z = acc[k];
      if(act) z = (z > 0.f) ? (z + 1.f) : __expf(z);   // 1 + elu
      out[n*64 + o] = z;
    }
  }
}

__global__ void __launch_bounds__(256) k_gemmQKV(const float* __restrict__ x,
    const float* __restrict__ Wq, const float* __restrict__ bq,
    const float* __restrict__ Wk, const float* __restrict__ bk,
    const float* __restrict__ Wv, const float* __restrict__ bv){
  int sel = blockIdx.y;
  const float* W = (sel==0) ? Wq : (sel==1) ? Wk : Wv;
  const float* b = (sel==0) ? bq : (sel==1) ? bk : bv;
  float* out = (sel==0) ? g_Q : (sel==1) ? g_Kf : g_V;
  gemm64_body(x, W, b, out, sel < 2);
}

__global__ void __launch_bounds__(256) k_gemmO(const float* __restrict__ Wo,
                                               const float* __restrict__ bo,
                                               float* __restrict__ dout){
  gemm64_body(g_hidden, Wo, bo, dout, false);
}

// ---------------- hop 1: M1 = A*(K outer V) [fp16 out], K1 = A*K [fp16 out],
//                  hidden = V*hop0 + g1*(Q.M1)/(Q.K1+CST)  (fp32 internal) ----------------
__global__ void __launch_bounds__(256) k_pass1(){
  int n    = (blockIdx.x*256 + threadIdx.x) >> 5;
  int lane = threadIdx.x & 31;
  int beg = colp(n), end = colp(n+1);
  int gb = lane & ~7;
  float m0[8], m1[8];
  #pragma unroll
  for(int j=0;j<8;j++){ m0[j]=0.f; m1[j]=0.f; }
  float ka0 = 0.f, ka1 = 0.f;
  for(int e=beg; e<end; e++){
    int row   = g_srow[e];
    float nrm = g_snorm[e];
    const float* Kr = &g_Kf[row*64];
    const float* Vr = &g_V[row*64];
    float k0 = Kr[lane], k1 = Kr[lane+32];
    float v0 = Vr[lane], v1 = Vr[lane+32];
    float a0 = nrm*k0, a1 = nrm*k1;
    ka0 += a0; ka1 += a1;
    #pragma unroll
    for(int j=0;j<8;j++){
      float vj0 = __shfl_sync(FULLMASK, v0, gb+j);
      float vj1 = __shfl_sync(FULLMASK, v1, gb+j);
      m0[j] = fmaf(a0, vj0, m0[j]);
      m1[j] = fmaf(a1, vj1, m1[j]);
    }
  }
  // store M1 fp16, natural layout el = h*64+i*8+j  (= lane*8+j / 256+lane*8+j)
  {
    union { uint4 u; __half2 h[4]; } p;
    p.h[0]=__floats2half2_rn(m0[0],m0[1]); p.h[1]=__floats2half2_rn(m0[2],m0[3]);
    p.h[2]=__floats2half2_rn(m0[4],m0[5]); p.h[3]=__floats2half2_rn(m0[6],m0[7]);
    *(uint4*)&g_M1h[(size_t)n*512 + lane*8] = p.u;
    p.h[0]=__floats2half2_rn(m1[0],m1[1]); p.h[1]=__floats2half2_rn(m1[2],m1[3]);
    p.h[2]=__floats2half2_rn(m1[4],m1[5]); p.h[3]=__floats2half2_rn(m1[6],m1[7]);
    *(uint4*)&g_M1h[(size_t)n*512 + 256 + lane*8] = p.u;
  }
  g_K1h[n*64+lane]    = __float2half_rn(ka0);
  g_K1h[n*64+lane+32] = __float2half_rn(ka1);

  // fused H1 = Q.M1 via smem transpose (row pad 9 -> conflict free)
  __shared__ float buf[8][576];
  float* bw = buf[threadIdx.x >> 5];
  #pragma unroll
  for(int j=0;j<8;j++){ bw[lane*9+j] = m0[j]; bw[(32+lane)*9+j] = m1[j]; }
  __syncwarp();
  float q0 = g_Q[n*64+lane], q1 = g_Q[n*64+lane+32];
  int j = lane & 7;
  float h0 = 0.f, h1 = 0.f;
  #pragma unroll
  for(int i=0;i<8;i++){
    float qi0 = __shfl_sync(FULLMASK, q0, gb+i);
    float qi1 = __shfl_sync(FULLMASK, q1, gb+i);
    h0 = fmaf(qi0, bw[(gb+i)*9 + j],    h0);
    h1 = fmaf(qi1, bw[(32+gb+i)*9 + j], h1);
  }
  float c0 = q0*ka0, c1 = q1*ka1;
  #pragma unroll
  for(int off=1; off<8; off<<=1){
    c0 += __shfl_xor_sync(FULLMASK, c0, off);
    c1 += __shfl_xor_sync(FULLMASK, c1, off);
  }
  c0 += CSTF; c1 += CSTF;
  float g0 = g_gamma[lane>>3], g1 = g_gamma[4 + (lane>>3)];
  float hp0 = g_hop0;
  float vv0 = g_V[n*64+lane], vv1 = g_V[n*64+lane+32];
  g_hidden[n*64+lane]    = fmaf(vv0, hp0, g0*h0/c0);
  g_hidden[n*64+lane+32] = fmaf(vv1, hp0, g1*h1/c1);
}

// ---------------- hop 2: hidden += g2*(Q.(A*M1))/(Q.(A*K1)+CST), fp16 reads, fp32 accum ----------------
// lane owns M elements el in [lane*16, lane*16+16); Q indices 2*lane, 2*lane+1; h = lane>>2
__global__ void __launch_bounds__(256) k_pass3(){
  int n    = (blockIdx.x*256 + threadIdx.x) >> 5;
  int lane = threadIdx.x & 31;
  int beg = colp(n), end = colp(n+1);
  float m[16];
  #pragma unroll
  for(int t=0;t<16;t++) m[t] = 0.f;
  float ca = 0.f, cb = 0.f;
  const __half* M1base = g_M1h;
  for(int e=beg; e<end; e++){
    int row   = g_srow[e];
    float nrm = g_snorm[e];
    const __half* Mr = &M1base[(size_t)row*512 + lane*16];
    uint4 a = *(const uint4*)Mr;
    uint4 b = *(const uint4*)(Mr + 8);
    __half2 kv = *(const __half2*)&g_K1h[row*64 + 2*lane];
    float2 f;
    f = __half22float2(*(__half2*)&a.x); m[0]=fmaf(nrm,f.x,m[0]);  m[1]=fmaf(nrm,f.y,m[1]);
    f = __half22float2(*(__half2*)&a.y); m[2]=fmaf(nrm,f.x,m[2]);  m[3]=fmaf(nrm,f.y,m[3]);
    f = __half22float2(*(__half2*)&a.z); m[4]=fmaf(nrm,f.x,m[4]);  m[5]=fmaf(nrm,f.y,m[5]);
    f = __half22float2(*(__half2*)&a.w); m[6]=fmaf(nrm,f.x,m[6]);  m[7]=fmaf(nrm,f.y,m[7]);
    f = __half22float2(*(__half2*)&b.x); m[8]=fmaf(nrm,f.x,m[8]);  m[9]=fmaf(nrm,f.y,m[9]);
    f = __half22float2(*(__half2*)&b.y); m[10]=fmaf(nrm,f.x,m[10]);m[11]=fmaf(nrm,f.y,m[11]);
    f = __half22float2(*(__half2*)&b.z); m[12]=fmaf(nrm,f.x,m[12]);m[13]=fmaf(nrm,f.y,m[13]);
    f = __half22float2(*(__half2*)&b.w); m[14]=fmaf(nrm,f.x,m[14]);m[15]=fmaf(nrm,f.y,m[15]);
    float2 kf = __half22float2(kv);
    ca = fmaf(nrm, kf.x, ca);
    cb = fmaf(nrm, kf.y, cb);
  }
  // contract with Q: lane's elements use Q[2*lane] (t<8) and Q[2*lane+1] (t>=8)
  float2 qv = *(const float2*)&g_Q[n*64 + 2*lane];
  float p[8];
  #pragma unroll
  for(int j=0;j<8;j++) p[j] = qv.x*m[j] + qv.y*m[8+j];
  #pragma unroll
  for(int j=0;j<8;j++){
    p[j] += __shfl_xor_sync(FULLMASK, p[j], 1);
    p[j] += __shfl_xor_sync(FULLMASK, p[j], 2);
  }
  float c = qv.x*ca + qv.y*cb;
  c += __shfl_xor_sync(FULLMASK, c, 1);
  c += __shfl_xor_sync(FULLMASK, c, 2);
  int h = lane >> 2, sub = lane & 3;
  float inv = g_gamma[8+h] / (c + CSTF);
  if(sub < 2){
    bool lo = (sub == 0);
    float r0 = lo ? p[0] : p[4];
    float r1 = lo ? p[1] : p[5];
    float r2 = lo ? p[2] : p[6];
    float r3 = lo ? p[3] : p[7];
    float4* hp = (float4*)&g_hidden[n*64 + h*8 + sub*4];
    float4 hv = *hp;
    hv.x += inv*r0; hv.y += inv*r1; hv.z += inv*r2; hv.w += inv*r3;
    *hp = hv;
  }
}

// ---------------- launch ----------------
extern "C" void kernel_launch(void* const* d_in, const int* in_sizes, int n_in,
                              void* d_out, int out_size){
  const float* x        = (const float*)d_in[0];
  const int*   ei       = (const int*)  d_in[1];
  const float* Wq       = (const float*)d_in[3];
  const float* bq       = (const float*)d_in[4];
  const float* Wk       = (const float*)d_in[5];
  const float* bk       = (const float*)d_in[6];
  const float* Wv       = (const float*)d_in[7];
  const float* bv       = (const float*)d_in[8];
  const float* Wo       = (const float*)d_in[9];
  const float* bo       = (const float*)d_in[10];
  const float* hopwise  = (const float*)d_in[11];
  const float* headwise = (const float*)d_in[12];
  float* out = (float*)d_out;

  k_init   <<<(2*NN+1023)/1024, 1024>>>(ei, hopwise, headwise);
  k_hist   <<<(NE+255)/256, 256>>>(ei);
  k_scan1  <<<NB, 256>>>();
  k_scan2  <<<1, 32>>>();
  k_scatter<<<(NE+255)/256, 256>>>(ei);
  {
    dim3 g((NN+63)/64, 3);
    k_gemmQKV<<<g, 256>>>(x, Wq, bq, Wk, bk, Wv, bv);
  }
  k_pass1  <<<NN/8, 256>>>();
  k_pass3  <<<NN/8, 256>>>();
  k_gemmO  <<<(NN+63)/64, 256>>>(Wo, bo, out);
}

// round 3
// speedup vs baseline: 1.6025x; 1.0800x over previous
#include <cuda_runtime.h>
#include <cuda_fp16.h>

#define NN 20000
#define NE 320000
#define NB 25
#define SEG 800
#define FULLMASK 0xffffffffu
#define CSTF 1e-5f

// ---------------- device scratch (static, zero at module load; every call restores zeros) ----
__device__ float  g_Q[NN*64];
__device__ __half g_Kh[NN*64];
__device__ __half g_Vh[NN*64];
__device__ float  g_V[NN*64];
__device__ float  g_hidden[NN*64];
__device__ __half g_M1h[(size_t)NN*512];   // [n]: pos<256 -> (K-row 2*(pos>>3), j=pos&7); pos>=256 -> row 2*((pos-256)>>3)+1
__device__ __half g_K1h[NN*64];            // [n][h*8+i]
__device__ float  g_deginv[NN];
__device__ int    g_cnt[NN];               // zeroed by k_scan1 after read
__device__ int    g_cur[NN];               // zeroed by k_pass1 tail
__device__ int    g_colptr[NN+1];          // block-local exclusive scan; [NN] stays 0
__device__ int    g_bsum[NB];
__device__ int    g_boff[NB+1];
__device__ int    g_srow[NE];
__device__ float  g_snorm[NE];

// int64-vs-int32 detect: sample 32 odd words; all zero => int64 (ids < 2^31 so high halves 0).
// P(false positive for int32) = (1/20000)^32 ~ 0. Word index < 640000 is safe for both layouts.
__device__ __forceinline__ void detect64(const int* __restrict__ ei, int tid, int* s64){
  if(tid < 32){
    bool z = (ei[2*(tid*9973)+1] == 0);
    unsigned bal = __ballot_sync(FULLMASK, z);
    if(tid==0) *s64 = (bal == FULLMASK) ? 1 : 0;
  }
}

__device__ __forceinline__ int colp(int i){
  return g_colptr[i] + g_boff[i/SEG];
}

// ---------------- histogram of in-degrees ----------------
__global__ void __launch_bounds__(256) k_hist(const int* __restrict__ ei){
  __shared__ int s64;
  int tid = threadIdx.x;
  detect64(ei, tid, &s64);
  __syncthreads();
  int e = blockIdx.x*256 + tid;   // grid covers NE exactly
  int c = s64 ? ei[2*(NE+e)] : ei[NE+e];
  atomicAdd(&g_cnt[c], 1);
}

// ---------------- per-segment exclusive scan + deginv; zeroes g_cnt for next replay ------
__global__ void __launch_bounds__(256) k_scan1(){
  __shared__ int s[SEG];
  __shared__ int wtot[8];
  int b = blockIdx.x, tid = threadIdx.x;
  for(int i=tid; i<SEG; i+=256){ s[i] = g_cnt[b*SEG+i]; g_cnt[b*SEG+i] = 0; }
  __syncthreads();
  int c0=0,c1=0,c2=0,c3=0,v=0;
  if(tid < 200){
    c0=s[4*tid]; c1=s[4*tid+1]; c2=s[4*tid+2]; c3=s[4*tid+3];
    v = c0+c1+c2+c3;
  }
  int lane = tid & 31, wid = tid >> 5;
  int x = v;
  #pragma unroll
  for(int off=1; off<32; off<<=1){ int y=__shfl_up_sync(FULLMASK,x,off); if(lane>=off) x+=y; }
  if(lane==31) wtot[wid] = x;
  __syncthreads();
  if(tid < 32){
    int w = (tid < 7) ? wtot[tid] : 0;
    #pragma unroll
    for(int off=1; off<32; off<<=1){ int y=__shfl_up_sync(FULLMASK,w,off); if(tid>=off) w+=y; }
    if(tid < 7) wtot[tid] = w;
    if(tid == 6) g_bsum[b] = w;
  }
  __syncthreads();
  if(tid < 200){
    int pre = x - v + (wid>0 ? wtot[wid-1] : 0);
    int base = b*SEG + 4*tid;
    g_colptr[base+0] = pre;
    g_colptr[base+1] = pre + c0;
    g_colptr[base+2] = pre + c0 + c1;
    g_colptr[base+3] = pre + c0 + c1 + c2;
    g_deginv[base+0] = c0 ? rsqrtf((float)c0) : 0.f;
    g_deginv[base+1] = c1 ? rsqrtf((float)c1) : 0.f;
    g_deginv[base+2] = c2 ? rsqrtf((float)c2) : 0.f;
    g_deginv[base+3] = c3 ? rsqrtf((float)c3) : 0.f;
  }
}

// ---------------- scatter edges into CSR; computes block offsets locally ----------------
__global__ void __launch_bounds__(256) k_scatter(const int* __restrict__ ei){
  __shared__ int s64;
  __shared__ int sboff[NB];
  int tid = threadIdx.x;
  detect64(ei, tid, &s64);
  if(tid >= 32 && tid < 64){
    int t = tid - 32;
    int v = (t < NB) ? g_bsum[t] : 0;
    int x = v;
    #pragma unroll
    for(int off=1; off<32; off<<=1){ int y=__shfl_up_sync(FULLMASK,x,off); if(t>=off) x+=y; }
    if(t < NB) sboff[t] = x - v;
    if(blockIdx.x == 0){
      if(t < NB) g_boff[t] = x - v;
      if(t == 31) g_boff[NB] = NE;
    }
  }
  __syncthreads();
  int e = blockIdx.x*256 + tid;
  int r = s64 ? ei[2*e]        : ei[e];
  int c = s64 ? ei[2*(NE+e)]   : ei[NE+e];
  int pos = g_colptr[c] + sboff[c/SEG] + atomicAdd(&g_cur[c], 1);
  g_srow[pos]  = r;
  g_snorm[pos] = g_deginv[r] * g_deginv[c];
}

// ---------------- dense 64x64 GEMMs ----------------
// mode: 0=Q (act, fp32), 1=K (act, fp16), 2=V (fp16 + fp32), 3=O (fp32 -> dout)
__device__ __forceinline__ void gemm64_body(const float* __restrict__ in,
                                            const float* __restrict__ W,
                                            const float* __restrict__ b,
                                            float* __restrict__ dout, int mode){
  __shared__ __align__(16) float xs[64*68];
  __shared__ float ws[64*64];
  __shared__ float bs[64];
  int nb = blockIdx.x*64;
  int tid = threadIdx.x;
  for(int idx = tid; idx < 4096; idx += 256){
    int n = idx >> 6, i = idx & 63;
    xs[n*68+i] = (nb+n < NN) ? in[(nb+n)*64 + i] : 0.f;
    ws[idx] = W[idx];
  }
  if(tid < 64) bs[tid] = b[tid];
  __syncthreads();
  int o  = tid & 63;
  int ng = (tid >> 6) << 4;
  float acc[16];
  #pragma unroll
  for(int k=0;k<16;k++) acc[k] = bs[o];
  #pragma unroll 4
  for(int i4=0; i4<64; i4+=4){
    float w0 = ws[(i4+0)*64+o], w1 = ws[(i4+1)*64+o];
    float w2 = ws[(i4+2)*64+o], w3 = ws[(i4+3)*64+o];
    #pragma unroll
    for(int k=0;k<16;k++){
      float4 xv = *(const float4*)&xs[(ng+k)*68 + i4];
      acc[k] = fmaf(xv.x, w0, fmaf(xv.y, w1, fmaf(xv.z, w2, fmaf(xv.w, w3, acc[k]))));
    }
  }
  #pragma unroll
  for(int k=0;k<16;k++){
    int n = nb + ng + k;
    if(n < NN){
      float z = acc[k];
      if(mode < 2) z = (z > 0.f) ? (z + 1.f) : __expf(z);   // 1 + elu
      if(mode == 0)      g_Q[n*64+o] = z;
      else if(mode == 1) g_Kh[n*64+o] = __float2half_rn(z);
      else if(mode == 2){ g_V[n*64+o] = z; g_Vh[n*64+o] = __float2half_rn(z); }
      else               dout[n*64+o] = z;
    }
  }
}

__global__ void __launch_bounds__(256) k_gemmQKV(const float* __restrict__ x,
    const float* __restrict__ Wq, const float* __restrict__ bq,
    const float* __restrict__ Wk, const float* __restrict__ bk,
    const float* __restrict__ Wv, const float* __restrict__ bv){
  int sel = blockIdx.y;
  const float* W = (sel==0) ? Wq : (sel==1) ? Wk : Wv;
  const float* b = (sel==0) ? bq : (sel==1) ? bk : bv;
  gemm64_body(x, W, b, nullptr, sel);
}

__global__ void __launch_bounds__(256) k_gemmO(const float* __restrict__ Wo,
                                               const float* __restrict__ bo,
                                               float* __restrict__ dout){
  gemm64_body(g_hidden, Wo, bo, dout, 3);
}

// ---------------- hop 1 ----------------
// lane owns K-rows (2*lane, 2*lane+1); h = lane>>2. Per edge: 2 half2 LDG + 4 shuffles.
__global__ void __launch_bounds__(256) k_pass1(const float* __restrict__ hopwise,
                                               const float* __restrict__ headwise){
  __shared__ float sgam[8];
  __shared__ float shop0;
  int tid = threadIdx.x;
  if(tid < 8){
    float mx = -1e30f;
    for(int hh=0; hh<8; hh++) mx = fmaxf(mx, headwise[hh*2]);
    float ss = 0.f;
    for(int hh=0; hh<8; hh++) ss += expf(headwise[hh*2]-mx);
    sgam[tid] = hopwise[1] * expf(headwise[tid*2]-mx) / ss;
  }
  if(tid == 8) shop0 = hopwise[0];
  __syncthreads();

  int n    = (blockIdx.x*256 + tid) >> 5;   // 2500 blocks * 8 warps = 20000
  int lane = tid & 31;
  int beg = colp(n), end = colp(n+1);
  float m0[8], m1[8];
  #pragma unroll
  for(int j=0;j<8;j++){ m0[j]=0.f; m1[j]=0.f; }
  float ka0 = 0.f, ka1 = 0.f;

  int row = 0; float nrm = 0.f;
  if(beg < end){ row = g_srow[beg]; nrm = g_snorm[beg]; }
  for(int e=beg; e<end; e++){
    int nrow = 0; float nnrm = 0.f;
    if(e+1 < end){ nrow = g_srow[e+1]; nnrm = g_snorm[e+1]; }
    __half2  kh = *(const __half2*) &g_Kh[row*64 + 2*lane];
    unsigned vu = *(const unsigned*)&g_Vh[row*64 + 2*lane];
    float2 kf = __half22float2(kh);
    float a0 = nrm*kf.x, a1 = nrm*kf.y;
    ka0 += a0; ka1 += a1;
    int base = lane & ~3;
    #pragma unroll
    for(int jj=0; jj<4; jj++){
      unsigned u = __shfl_sync(FULLMASK, vu, base + jj);
      float2 vf = __half22float2(*(__half2*)&u);
      m0[2*jj]   = fmaf(a0, vf.x, m0[2*jj]);
      m0[2*jj+1] = fmaf(a0, vf.y, m0[2*jj+1]);
      m1[2*jj]   = fmaf(a1, vf.x, m1[2*jj]);
      m1[2*jj+1] = fmaf(a1, vf.y, m1[2*jj+1]);
    }
    row = nrow; nrm = nnrm;
  }

  // store M1 (fp16): lane's chunks at [lane*8] (row 2*lane) and [256+lane*8] (row 2*lane+1)
  {
    union { uint4 u; __half2 h[4]; } p;
    p.h[0]=__floats2half2_rn(m0[0],m0[1]); p.h[1]=__floats2half2_rn(m0[2],m0[3]);
    p.h[2]=__floats2half2_rn(m0[4],m0[5]); p.h[3]=__floats2half2_rn(m0[6],m0[7]);
    *(uint4*)&g_M1h[(size_t)n*512 + lane*8] = p.u;
    p.h[0]=__floats2half2_rn(m1[0],m1[1]); p.h[1]=__floats2half2_rn(m1[2],m1[3]);
    p.h[2]=__floats2half2_rn(m1[4],m1[5]); p.h[3]=__floats2half2_rn(m1[6],m1[7]);
    *(uint4*)&g_M1h[(size_t)n*512 + 256 + lane*8] = p.u;
  }
  *(__half2*)&g_K1h[n*64 + 2*lane] = __floats2half2_rn(ka0, ka1);

  // epilogue: H1 = Q.M1, C1 = Q.K1 + CST, hidden = V*hop0 + g1*H1/C1
  float2 qv = *(const float2*)&g_Q[n*64 + 2*lane];
  float p[8];
  #pragma unroll
  for(int j=0;j<8;j++) p[j] = qv.x*m0[j] + qv.y*m1[j];
  #pragma unroll
  for(int j=0;j<8;j++){
    p[j] += __shfl_xor_sync(FULLMASK, p[j], 1);
    p[j] += __shfl_xor_sync(FULLMASK, p[j], 2);
  }
  float c = qv.x*ka0 + qv.y*ka1;
  c += __shfl_xor_sync(FULLMASK, c, 1);
  c += __shfl_xor_sync(FULLMASK, c, 2);
  int h = lane >> 2, sub = lane & 3;
  if(sub < 2){
    bool lo = (sub == 0);
    float r0 = lo ? p[0] : p[4];
    float r1 = lo ? p[1] : p[5];
    float r2 = lo ? p[2] : p[6];
    float r3 = lo ? p[3] : p[7];
    float inv = sgam[h] / (c + CSTF);
    float hp0 = shop0;
    const float4 vv = *(const float4*)&g_V[n*64 + h*8 + sub*4];
    float4 hv;
    hv.x = fmaf(vv.x, hp0, inv*r0);
    hv.y = fmaf(vv.y, hp0, inv*r1);
    hv.z = fmaf(vv.z, hp0, inv*r2);
    hv.w = fmaf(vv.w, hp0, inv*r3);
    *(float4*)&g_hidden[n*64 + h*8 + sub*4] = hv;
  }
  if(lane == 0) g_cur[n] = 0;   // restore for next graph replay
}

// ---------------- hop 2 ----------------
__global__ void __launch_bounds__(256) k_pass3(const float* __restrict__ hopwise,
                                               const float* __restrict__ headwise){
  __shared__ float sgam[8];
  int tid = threadIdx.x;
  if(tid < 8){
    float mx = -1e30f;
    for(int hh=0; hh<8; hh++) mx = fmaxf(mx, headwise[hh*2+1]);
    float ss = 0.f;
    for(int hh=0; hh<8; hh++) ss += expf(headwise[hh*2+1]-mx);
    sgam[tid] = hopwise[2] * expf(headwise[tid*2+1]-mx) / ss;
  }
  __syncthreads();

  int n    = (blockIdx.x*256 + tid) >> 5;
  int lane = tid & 31;
  int beg = colp(n), end = colp(n+1);
  float m[16];
  #pragma unroll
  for(int t=0;t<16;t++) m[t] = 0.f;
  float ca = 0.f, cb = 0.f;

  int row = 0; float nrm = 0.f;
  if(beg < end){ row = g_srow[beg]; nrm = g_snorm[beg]; }
  for(int e=beg; e<end; e++){
    int nrow = 0; float nnrm = 0.f;
    if(e+1 < end){ nrow = g_srow[e+1]; nnrm = g_snorm[e+1]; }
    const __half* Mr = &g_M1h[(size_t)row*512];
    uint4 a = *(const uint4*)(Mr + lane*8);         // K-row 2*lane,   j=0..7
    uint4 b = *(const uint4*)(Mr + 256 + lane*8);   // K-row 2*lane+1, j=0..7
    __half2 kv = *(const __half2*)&g_K1h[row*64 + 2*lane];
    float2 f;
    f = __half22float2(*(__half2*)&a.x); m[0]=fmaf(nrm,f.x,m[0]);   m[1]=fmaf(nrm,f.y,m[1]);
    f = __half22float2(*(__half2*)&a.y); m[2]=fmaf(nrm,f.x,m[2]);   m[3]=fmaf(nrm,f.y,m[3]);
    f = __half22float2(*(__half2*)&a.z); m[4]=fmaf(nrm,f.x,m[4]);   m[5]=fmaf(nrm,f.y,m[5]);
    f = __half22float2(*(__half2*)&a.w); m[6]=fmaf(nrm,f.x,m[6]);   m[7]=fmaf(nrm,f.y,m[7]);
    f = __half22float2(*(__half2*)&b.x); m[8]=fmaf(nrm,f.x,m[8]);   m[9]=fmaf(nrm,f.y,m[9]);
    f = __half22float2(*(__half2*)&b.y); m[10]=fmaf(nrm,f.x,m[10]); m[11]=fmaf(nrm,f.y,m[11]);
    f = __half22float2(*(__half2*)&b.z); m[12]=fmaf(nrm,f.x,m[12]); m[13]=fmaf(nrm,f.y,m[13]);
    f = __half22float2(*(__half2*)&b.w); m[14]=fmaf(nrm,f.x,m[14]); m[15]=fmaf(nrm,f.y,m[15]);
    float2 kf = __half22float2(kv);
    ca = fmaf(nrm, kf.x, ca);
    cb = fmaf(nrm, kf.y, cb);
    row = nrow; nrm = nnrm;
  }

  float2 qv = *(const float2*)&g_Q[n*64 + 2*lane];
  float p[8];
  #pragma unroll
  for(int j=0;j<8;j++) p[j] = qv.x*m[j] + qv.y*m[8+j];
  #pragma unroll
  for(int j=0;j<8;j++){
    p[j] += __shfl_xor_sync(FULLMASK, p[j], 1);
    p[j] += __shfl_xor_sync(FULLMASK, p[j], 2);
  }
  float c = qv.x*ca + qv.y*cb;
  c += __shfl_xor_sync(FULLMASK, c, 1);
  c += __shfl_xor_sync(FULLMASK, c, 2);
  int h = lane >> 2, sub = lane & 3;
  if(sub < 2){
    bool lo = (sub == 0);
    float r0 = lo ? p[0] : p[4];
    float r1 = lo ? p[1] : p[5];
    float r2 = lo ? p[2] : p[6];
    float r3 = lo ? p[3] : p[7];
    float inv = sgam[h] / (c + CSTF);
    float4* hp = (float4*)&g_hidden[n*64 + h*8 + sub*4];
    float4 hv = *hp;
    hv.x += inv*r0; hv.y += inv*r1; hv.z += inv*r2; hv.w += inv*r3;
    *hp = hv;
  }
}

// ---------------- launch ----------------
extern "C" void kernel_launch(void* const* d_in, const int* in_sizes, int n_in,
                              void* d_out, int out_size){
  const float* x        = (const float*)d_in[0];
  const int*   ei       = (const int*)  d_in[1];
  const float* Wq       = (const float*)d_in[3];
  const float* bq       = (const float*)d_in[4];
  const float* Wk       = (const float*)d_in[5];
  const float* bk       = (const float*)d_in[6];
  const float* Wv       = (const float*)d_in[7];
  const float* bv       = (const float*)d_in[8];
  const float* Wo       = (const float*)d_in[9];
  const float* bo       = (const float*)d_in[10];
  const float* hopwise  = (const float*)d_in[11];
  const float* headwise = (const float*)d_in[12];
  float* out = (float*)d_out;

  k_hist   <<<NE/256, 256>>>(ei);
  k_scan1  <<<NB, 256>>>();
  k_scatter<<<NE/256, 256>>>(ei);
  {
    dim3 g((NN+63)/64, 3);
    k_gemmQKV<<<g, 256>>>(x, Wq, bq, Wk, bk, Wv, bv);
  }
  k_pass1  <<<NN/8, 256>>>(hopwise, headwise);
  k_pass3  <<<NN/8, 256>>>(hopwise, headwise);
  k_gemmO  <<<(NN+63)/64, 256>>>(Wo, bo, out);
}

// round 4
// speedup vs baseline: 1.6465x; 1.0275x over previous
#include <cuda_runtime.h>
#include <cuda_fp16.h>

#define NN 20000
#define NE 320000
#define NB 25
#define SEG 800
#define FULLMASK 0xffffffffu
#define CSTF 1e-5f

// ---------------- device scratch (static, zero at module load; every call restores zeros) ----
__device__ float  g_Q[NN*64];
__device__ __half g_Kh[NN*64];
__device__ __half g_Vh[NN*64];
__device__ float  g_V[NN*64];
__device__ float  g_hidden[NN*64];
__device__ __half g_M1h[(size_t)NN*512];
__device__ __half g_K1h[NN*64];
__device__ float  g_deginv[NN];
__device__ int    g_cnt[NN];               // zeroed by k_scan1 after read
__device__ int    g_cur[NN];               // zeroed by k_pass1 tail
__device__ int    g_colptr[NN+1];
__device__ int    g_bsum[NB];
__device__ int    g_boff[NB+1];
__device__ int    g_srow[NE];
__device__ float  g_snorm[NE];

// int64-vs-int32 detect: sample 32 odd words; all zero => int64.
__device__ __forceinline__ void detect64(const int* __restrict__ ei, int tid, int* s64){
  if(tid < 32){
    bool z = (ei[2*(tid*9973)+1] == 0);
    unsigned bal = __ballot_sync(FULLMASK, z);
    if(tid==0) *s64 = (bal == FULLMASK) ? 1 : 0;
  }
}

__device__ __forceinline__ int colp(int i){
  return g_colptr[i] + g_boff[i/SEG];
}

// ---------------- histogram of in-degrees ----------------
__global__ void __launch_bounds__(256) k_hist(const int* __restrict__ ei){
  __shared__ int s64;
  int tid = threadIdx.x;
  detect64(ei, tid, &s64);
  __syncthreads();
  int e = blockIdx.x*256 + tid;
  int c = s64 ? ei[2*(NE+e)] : ei[NE+e];
  atomicAdd(&g_cnt[c], 1);
}

// ---------------- per-segment exclusive scan + deginv; zeroes g_cnt ----------------
__global__ void __launch_bounds__(256) k_scan1(){
  __shared__ int s[SEG];
  __shared__ int wtot[8];
  int b = blockIdx.x, tid = threadIdx.x;
  for(int i=tid; i<SEG; i+=256){ s[i] = g_cnt[b*SEG+i]; g_cnt[b*SEG+i] = 0; }
  __syncthreads();
  int c0=0,c1=0,c2=0,c3=0,v=0;
  if(tid < 200){
    c0=s[4*tid]; c1=s[4*tid+1]; c2=s[4*tid+2]; c3=s[4*tid+3];
    v = c0+c1+c2+c3;
  }
  int lane = tid & 31, wid = tid >> 5;
  int x = v;
  #pragma unroll
  for(int off=1; off<32; off<<=1){ int y=__shfl_up_sync(FULLMASK,x,off); if(lane>=off) x+=y; }
  if(lane==31) wtot[wid] = x;
  __syncthreads();
  if(tid < 32){
    int w = (tid < 7) ? wtot[tid] : 0;
    #pragma unroll
    for(int off=1; off<32; off<<=1){ int y=__shfl_up_sync(FULLMASK,w,off); if(tid>=off) w+=y; }
    if(tid < 7) wtot[tid] = w;
    if(tid == 6) g_bsum[b] = w;
  }
  __syncthreads();
  if(tid < 200){
    int pre = x - v + (wid>0 ? wtot[wid-1] : 0);
    int base = b*SEG + 4*tid;
    g_colptr[base+0] = pre;
    g_colptr[base+1] = pre + c0;
    g_colptr[base+2] = pre + c0 + c1;
    g_colptr[base+3] = pre + c0 + c1 + c2;
    g_deginv[base+0] = c0 ? rsqrtf((float)c0) : 0.f;
    g_deginv[base+1] = c1 ? rsqrtf((float)c1) : 0.f;
    g_deginv[base+2] = c2 ? rsqrtf((float)c2) : 0.f;
    g_deginv[base+3] = c3 ? rsqrtf((float)c3) : 0.f;
  }
}

// ---------------- scatter edges into CSR ----------------
__global__ void __launch_bounds__(256) k_scatter(const int* __restrict__ ei){
  __shared__ int s64;
  __shared__ int sboff[NB];
  int tid = threadIdx.x;
  detect64(ei, tid, &s64);
  if(tid >= 32 && tid < 64){
    int t = tid - 32;
    int v = (t < NB) ? g_bsum[t] : 0;
    int x = v;
    #pragma unroll
    for(int off=1; off<32; off<<=1){ int y=__shfl_up_sync(FULLMASK,x,off); if(t>=off) x+=y; }
    if(t < NB) sboff[t] = x - v;
    if(blockIdx.x == 0){
      if(t < NB) g_boff[t] = x - v;
      if(t == 31) g_boff[NB] = NE;
    }
  }
  __syncthreads();
  int e = blockIdx.x*256 + tid;
  int r = s64 ? ei[2*e]        : ei[e];
  int c = s64 ? ei[2*(NE+e)]   : ei[NE+e];
  int pos = g_colptr[c] + sboff[c/SEG] + atomicAdd(&g_cur[c], 1);
  g_srow[pos]  = r;
  g_snorm[pos] = g_deginv[r] * g_deginv[c];
}

// ---------------- merged QKV GEMM: one xs tile, 3 weight mats (fp16 in smem) ------------
// thread tile: 8 nodes x 2 outputs (o, o+32) x 3 mats = 48 accumulators.
__global__ void __launch_bounds__(256) k_gemmQKV(const float* __restrict__ x,
    const float* __restrict__ Wq, const float* __restrict__ bq,
    const float* __restrict__ Wk, const float* __restrict__ bk,
    const float* __restrict__ Wv, const float* __restrict__ bv){
  __shared__ __align__(16) float xs[64*68];
  __shared__ __align__(8)  __half ws[3][64*68];   // transposed: ws[m][o*68 + i]
  __shared__ float bs[3][64];
  int nb = blockIdx.x*64;
  int tid = threadIdx.x;
  for(int idx = tid; idx < 4096; idx += 256){
    int n = idx >> 6, i = idx & 63;
    xs[n*68+i] = (nb+n < NN) ? x[(nb+n)*64 + i] : 0.f;
    int o = i, ii = n;      // reread as (i=idx>>6, o=idx&63) for coalesced W reads
    ws[0][o*68+ii] = __float2half_rn(Wq[idx]);
    ws[1][o*68+ii] = __float2half_rn(Wk[idx]);
    ws[2][o*68+ii] = __float2half_rn(Wv[idx]);
  }
  if(tid < 64){ bs[0][tid]=bq[tid]; bs[1][tid]=bk[tid]; bs[2][tid]=bv[tid]; }
  __syncthreads();

  int o  = tid & 31;
  int ng = (tid >> 5) << 3;
  float acc[3][16];
  #pragma unroll
  for(int m=0;m<3;m++)
    #pragma unroll
    for(int g=0;g<8;g++){ acc[m][2*g] = bs[m][o]; acc[m][2*g+1] = bs[m][o+32]; }

  #pragma unroll 2
  for(int i4=0; i4<64; i4+=4){
    float wv[3][2][4];
    #pragma unroll
    for(int m=0;m<3;m++){
      #pragma unroll
      for(int t=0;t<2;t++){
        uint2 u = *(const uint2*)&ws[m][(o+32*t)*68 + i4];
        float2 a = __half22float2(*(__half2*)&u.x);
        float2 b = __half22float2(*(__half2*)&u.y);
        wv[m][t][0]=a.x; wv[m][t][1]=a.y; wv[m][t][2]=b.x; wv[m][t][3]=b.y;
      }
    }
    #pragma unroll
    for(int g=0;g<8;g++){
      float4 xv = *(const float4*)&xs[(ng+g)*68 + i4];
      #pragma unroll
      for(int m=0;m<3;m++){
        #pragma unroll
        for(int t=0;t<2;t++){
          acc[m][2*g+t] = fmaf(xv.x, wv[m][t][0],
                          fmaf(xv.y, wv[m][t][1],
                          fmaf(xv.z, wv[m][t][2],
                          fmaf(xv.w, wv[m][t][3], acc[m][2*g+t]))));
        }
      }
    }
  }

  #pragma unroll
  for(int g=0;g<8;g++){
    int n = nb + ng + g;
    if(n < NN){
      // Q: 1+elu, fp32
      float q0 = acc[0][2*g],  q1 = acc[0][2*g+1];
      q0 = (q0 > 0.f) ? (q0 + 1.f) : __expf(q0);
      q1 = (q1 > 0.f) ? (q1 + 1.f) : __expf(q1);
      g_Q[n*64+o] = q0; g_Q[n*64+o+32] = q1;
      // K: 1+elu, fp16
      float k0 = acc[1][2*g],  k1 = acc[1][2*g+1];
      k0 = (k0 > 0.f) ? (k0 + 1.f) : __expf(k0);
      k1 = (k1 > 0.f) ? (k1 + 1.f) : __expf(k1);
      g_Kh[n*64+o] = __float2half_rn(k0); g_Kh[n*64+o+32] = __float2half_rn(k1);
      // V: fp32 + fp16
      float v0 = acc[2][2*g],  v1 = acc[2][2*g+1];
      g_V[n*64+o] = v0; g_V[n*64+o+32] = v1;
      g_Vh[n*64+o] = __float2half_rn(v0); g_Vh[n*64+o+32] = __float2half_rn(v1);
    }
  }
}

// ---------------- output GEMM: hidden @ Wo + bo -> dout ----------------
__global__ void __launch_bounds__(256) k_gemmO(const float* __restrict__ Wo,
                                               const float* __restrict__ bo,
                                               float* __restrict__ dout){
  __shared__ __align__(16) float xs[64*68];
  __shared__ __align__(8)  __half ws[64*68];
  __shared__ float bs[64];
  int nb = blockIdx.x*64;
  int tid = threadIdx.x;
  for(int idx = tid; idx < 4096; idx += 256){
    int n = idx >> 6, i = idx & 63;
    xs[n*68+i] = (nb+n < NN) ? g_hidden[(nb+n)*64 + i] : 0.f;
    ws[(idx&63)*68 + (idx>>6)] = __float2half_rn(Wo[idx]);
  }
  if(tid < 64) bs[tid] = bo[tid];
  __syncthreads();

  int o  = tid & 31;
  int ng = (tid >> 5) << 3;
  float acc[16];
  #pragma unroll
  for(int g=0;g<8;g++){ acc[2*g] = bs[o]; acc[2*g+1] = bs[o+32]; }

  #pragma unroll 2
  for(int i4=0; i4<64; i4+=4){
    float wv[2][4];
    #pragma unroll
    for(int t=0;t<2;t++){
      uint2 u = *(const uint2*)&ws[(o+32*t)*68 + i4];
      float2 a = __half22float2(*(__half2*)&u.x);
      float2 b = __half22float2(*(__half2*)&u.y);
      wv[t][0]=a.x; wv[t][1]=a.y; wv[t][2]=b.x; wv[t][3]=b.y;
    }
    #pragma unroll
    for(int g=0;g<8;g++){
      float4 xv = *(const float4*)&xs[(ng+g)*68 + i4];
      #pragma unroll
      for(int t=0;t<2;t++){
        acc[2*g+t] = fmaf(xv.x, wv[t][0],
                     fmaf(xv.y, wv[t][1],
                     fmaf(xv.z, wv[t][2],
                     fmaf(xv.w, wv[t][3], acc[2*g+t]))));
      }
    }
  }
  #pragma unroll
  for(int g=0;g<8;g++){
    int n = nb + ng + g;
    if(n < NN){
      dout[n*64+o]    = acc[2*g];
      dout[n*64+o+32] = acc[2*g+1];
    }
  }
}

// ---------------- hop 1 ----------------
__global__ void __launch_bounds__(256) k_pass1(const float* __restrict__ hopwise,
                                               const float* __restrict__ headwise){
  __shared__ float sgam[8];
  __shared__ float shop0;
  int tid = threadIdx.x;
  if(tid < 8){
    float mx = -1e30f;
    for(int hh=0; hh<8; hh++) mx = fmaxf(mx, headwise[hh*2]);
    float ss = 0.f;
    for(int hh=0; hh<8; hh++) ss += expf(headwise[hh*2]-mx);
    sgam[tid] = hopwise[1] * expf(headwise[tid*2]-mx) / ss;
  }
  if(tid == 8) shop0 = hopwise[0];
  __syncthreads();

  int n    = (blockIdx.x*256 + tid) >> 5;
  int lane = tid & 31;
  int beg = colp(n), end = colp(n+1);
  float m0[8], m1[8];
  #pragma unroll
  for(int j=0;j<8;j++){ m0[j]=0.f; m1[j]=0.f; }
  float ka0 = 0.f, ka1 = 0.f;

  int row = 0; float nrm = 0.f;
  if(beg < end){ row = g_srow[beg]; nrm = g_snorm[beg]; }
  for(int e=beg; e<end; e++){
    int nrow = 0; float nnrm = 0.f;
    if(e+1 < end){ nrow = g_srow[e+1]; nnrm = g_snorm[e+1]; }
    __half2  kh = *(const __half2*) &g_Kh[row*64 + 2*lane];
    unsigned vu = *(const unsigned*)&g_Vh[row*64 + 2*lane];
    float2 kf = __half22float2(kh);
    float a0 = nrm*kf.x, a1 = nrm*kf.y;
    ka0 += a0; ka1 += a1;
    int base = lane & ~3;
    #pragma unroll
    for(int jj=0; jj<4; jj++){
      unsigned u = __shfl_sync(FULLMASK, vu, base + jj);
      float2 vf = __half22float2(*(__half2*)&u);
      m0[2*jj]   = fmaf(a0, vf.x, m0[2*jj]);
      m0[2*jj+1] = fmaf(a0, vf.y, m0[2*jj+1]);
      m1[2*jj]   = fmaf(a1, vf.x, m1[2*jj]);
      m1[2*jj+1] = fmaf(a1, vf.y, m1[2*jj+1]);
    }
    row = nrow; nrm = nnrm;
  }

  {
    union { uint4 u; __half2 h[4]; } p;
    p.h[0]=__floats2half2_rn(m0[0],m0[1]); p.h[1]=__floats2half2_rn(m0[2],m0[3]);
    p.h[2]=__floats2half2_rn(m0[4],m0[5]); p.h[3]=__floats2half2_rn(m0[6],m0[7]);
    *(uint4*)&g_M1h[(size_t)n*512 + lane*8] = p.u;
    p.h[0]=__floats2half2_rn(m1[0],m1[1]); p.h[1]=__floats2half2_rn(m1[2],m1[3]);
    p.h[2]=__floats2half2_rn(m1[4],m1[5]); p.h[3]=__floats2half2_rn(m1[6],m1[7]);
    *(uint4*)&g_M1h[(size_t)n*512 + 256 + lane*8] = p.u;
  }
  *(__half2*)&g_K1h[n*64 + 2*lane] = __floats2half2_rn(ka0, ka1);

  float2 qv = *(const float2*)&g_Q[n*64 + 2*lane];
  float p[8];
  #pragma unroll
  for(int j=0;j<8;j++) p[j] = qv.x*m0[j] + qv.y*m1[j];
  #pragma unroll
  for(int j=0;j<8;j++){
    p[j] += __shfl_xor_sync(FULLMASK, p[j], 1);
    p[j] += __shfl_xor_sync(FULLMASK, p[j], 2);
  }
  float c = qv.x*ka0 + qv.y*ka1;
  c += __shfl_xor_sync(FULLMASK, c, 1);
  c += __shfl_xor_sync(FULLMASK, c, 2);
  int h = lane >> 2, sub = lane & 3;
  if(sub < 2){
    bool lo = (sub == 0);
    float r0 = lo ? p[0] : p[4];
    float r1 = lo ? p[1] : p[5];
    float r2 = lo ? p[2] : p[6];
    float r3 = lo ? p[3] : p[7];
    float inv = sgam[h] / (c + CSTF);
    float hp0 = shop0;
    const float4 vv = *(const float4*)&g_V[n*64 + h*8 + sub*4];
    float4 hv;
    hv.x = fmaf(vv.x, hp0, inv*r0);
    hv.y = fmaf(vv.y, hp0, inv*r1);
    hv.z = fmaf(vv.z, hp0, inv*r2);
    hv.w = fmaf(vv.w, hp0, inv*r3);
    *(float4*)&g_hidden[n*64 + h*8 + sub*4] = hv;
  }
  if(lane == 0) g_cur[n] = 0;
}

// ---------------- hop 2 ----------------
__global__ void __launch_bounds__(256) k_pass3(const float* __restrict__ hopwise,
                                               const float* __restrict__ headwise){
  __shared__ float sgam[8];
  int tid = threadIdx.x;
  if(tid < 8){
    float mx = -1e30f;
    for(int hh=0; hh<8; hh++) mx = fmaxf(mx, headwise[hh*2+1]);
    float ss = 0.f;
    for(int hh=0; hh<8; hh++) ss += expf(headwise[hh*2+1]-mx);
    sgam[tid] = hopwise[2] * expf(headwise[tid*2+1]-mx) / ss;
  }
  __syncthreads();

  int n    = (blockIdx.x*256 + tid) >> 5;
  int lane = tid & 31;
  int beg = colp(n), end = colp(n+1);
  float m[16];
  #pragma unroll
  for(int t=0;t<16;t++) m[t] = 0.f;
  float ca = 0.f, cb = 0.f;

  int row = 0; float nrm = 0.f;
  if(beg < end){ row = g_srow[beg]; nrm = g_snorm[beg]; }
  for(int e=beg; e<end; e++){
    int nrow = 0; float nnrm = 0.f;
    if(e+1 < end){ nrow = g_srow[e+1]; nnrm = g_snorm[e+1]; }
    const __half* Mr = &g_M1h[(size_t)row*512];
    uint4 a = *(const uint4*)(Mr + lane*8);
    uint4 b = *(const uint4*)(Mr + 256 + lane*8);
    __half2 kv = *(const __half2*)&g_K1h[row*64 + 2*lane];
    float2 f;
    f = __half22float2(*(__half2*)&a.x); m[0]=fmaf(nrm,f.x,m[0]);   m[1]=fmaf(nrm,f.y,m[1]);
    f = __half22float2(*(__half2*)&a.y); m[2]=fmaf(nrm,f.x,m[2]);   m[3]=fmaf(nrm,f.y,m[3]);
    f = __half22float2(*(__half2*)&a.z); m[4]=fmaf(nrm,f.x,m[4]);   m[5]=fmaf(nrm,f.y,m[5]);
    f = __half22float2(*(__half2*)&a.w); m[6]=fmaf(nrm,f.x,m[6]);   m[7]=fmaf(nrm,f.y,m[7]);
    f = __half22float2(*(__half2*)&b.x); m[8]=fmaf(nrm,f.x,m[8]);   m[9]=fmaf(nrm,f.y,m[9]);
    f = __half22float2(*(__half2*)&b.y); m[10]=fmaf(nrm,f.x,m[10]); m[11]=fmaf(nrm,f.y,m[11]);
    f = __half22float2(*(__half2*)&b.z); m[12]=fmaf(nrm,f.x,m[12]); m[13]=fmaf(nrm,f.y,m[13]);
    f = __half22float2(*(__half2*)&b.w); m[14]=fmaf(nrm,f.x,m[14]); m[15]=fmaf(nrm,f.y,m[15]);
    float2 kf = __half22float2(kv);
    ca = fmaf(nrm, kf.x, ca);
    cb = fmaf(nrm, kf.y, cb);
    row = nrow; nrm = nnrm;
  }

  float2 qv = *(const float2*)&g_Q[n*64 + 2*lane];
  float p[8];
  #pragma unroll
  for(int j=0;j<8;j++) p[j] = qv.x*m[j] + qv.y*m[8+j];
  #pragma unroll
  for(int j=0;j<8;j++){
    p[j] += __shfl_xor_sync(FULLMASK, p[j], 1);
    p[j] += __shfl_xor_sync(FULLMASK, p[j], 2);
  }
  float c = qv.x*ca + qv.y*cb;
  c += __shfl_xor_sync(FULLMASK, c, 1);
  c += __shfl_xor_sync(FULLMASK, c, 2);
  int h = lane >> 2, sub = lane & 3;
  if(sub < 2){
    bool lo = (sub == 0);
    float r0 = lo ? p[0] : p[4];
    float r1 = lo ? p[1] : p[5];
    float r2 = lo ? p[2] : p[6];
    float r3 = lo ? p[3] : p[7];
    float inv = sgam[h] / (c + CSTF);
    float4* hp = (float4*)&g_hidden[n*64 + h*8 + sub*4];
    float4 hv = *hp;
    hv.x += inv*r0; hv.y += inv*r1; hv.z += inv*r2; hv.w += inv*r3;
    *hp = hv;
  }
}

// ---------------- launch ----------------
extern "C" void kernel_launch(void* const* d_in, const int* in_sizes, int n_in,
                              void* d_out, int out_size){
  const float* x        = (const float*)d_in[0];
  const int*   ei       = (const int*)  d_in[1];
  const float* Wq       = (const float*)d_in[3];
  const float* bq       = (const float*)d_in[4];
  const float* Wk       = (const float*)d_in[5];
  const float* bk       = (const float*)d_in[6];
  const float* Wv       = (const float*)d_in[7];
  const float* bv       = (const float*)d_in[8];
  const float* Wo       = (const float*)d_in[9];
  const float* bo       = (const float*)d_in[10];
  const float* hopwise  = (const float*)d_in[11];
  const float* headwise = (const float*)d_in[12];
  float* out = (float*)d_out;

  k_hist   <<<NE/256, 256>>>(ei);
  k_scan1  <<<NB, 256>>>();
  k_scatter<<<NE/256, 256>>>(ei);
  k_gemmQKV<<<(NN+63)/64, 256>>>(x, Wq, bq, Wk, bk, Wv, bv);
  k_pass1  <<<NN/8, 256>>>(hopwise, headwise);
  k_pass3  <<<NN/8, 256>>>(hopwise, headwise);
  k_gemmO  <<<(NN+63)/64, 256>>>(Wo, bo, out);
}